// round 2
// baseline (speedup 1.0000x reference)
#include <cuda_runtime.h>
#include <cuda_bf16.h>

// ---------------------------------------------------------------------------
// PointNet++ encoder, B=2, N=16384, 4 SA stages (stride 4, nsample 32)
// ---------------------------------------------------------------------------

// ---------------- scratch buffers (device globals; no allocs allowed) ------
__device__ float g_f0[8585216];    // gathered features  max: 2*131*1024*32
__device__ float g_h1[16777216];   // layer-1 out        max: 2*64*4096*32
__device__ float g_h2[16777216];   // layer-2 out        max: 2*64*4096*32
__device__ float g_fA[1048576];    // pooled feats ping  max: 2*128*4096
__device__ float g_fB[1048576];    // pooled feats pong
__device__ float g_feats0[98304];  // xyz^T              2*3*16384
__device__ float g_q0[24576];      // query xyz ping     2*4096*3
__device__ float g_q1[24576];      // query xyz pong
__device__ int   g_fpsidx[8192];   // 2*4096
__device__ int   g_ballidx[262144];// 2*4096*32

__device__ __forceinline__ const float* fbufc(int code, const float* ext) {
    switch (code) {
        case 0: return g_f0;  case 1: return g_h1;  case 2: return g_h2;
        case 3: return g_fA;  case 4: return g_fB;  case 5: return g_feats0;
        case 6: return g_q0;  case 7: return g_q1;  default: return ext;
    }
}
__device__ __forceinline__ float* fbufw(int code, float* ext) {
    switch (code) {
        case 0: return g_f0;  case 1: return g_h1;  case 2: return g_h2;
        case 3: return g_fA;  case 4: return g_fB;  case 5: return g_feats0;
        case 6: return g_q0;  case 7: return g_q1;  default: return ext;
    }
}

// d2 exactly as JAX computes it: ((dx*dx + dy*dy) + dz*dz), no FMA contraction
__device__ __forceinline__ float d2_exact(float dx, float dy, float dz) {
    return __fadd_rn(__fadd_rn(__fmul_rn(dx, dx), __fmul_rn(dy, dy)),
                     __fmul_rn(dz, dz));
}

// ---------------- feats0 = xyz^T  [B,3,N] -----------------------------------
__global__ void k_transpose(const float* __restrict__ xyz) {
    int i = blockIdx.x * blockDim.x + threadIdx.x;
    if (i >= 2 * 16384) return;
    int b = i >> 14, n = i & 16383;
#pragma unroll
    for (int c = 0; c < 3; ++c)
        g_feats0[(b * 3 + c) * 16384 + n] = xyz[(size_t)i * 3 + c];
}

// ---------------- furthest point sampling -----------------------------------
// One CTA per batch (strictly sequential argmax chain). Coords live in smem,
// per-thread min-dists in registers. Tie-break: smallest index (jnp.argmax).
__global__ __launch_bounds__(1024, 1)
void k_fps(const float* __restrict__ ext, int scode, int N, int npoint) {
    extern __shared__ float sm[];
    float* sx = sm; float* sy = sm + N; float* sz = sm + 2 * N;
    __shared__ unsigned long long warpbest[32];
    __shared__ int s_last;

    int b = blockIdx.x;
    int tid = threadIdx.x;
    const float* p = fbufc(scode, ext) + (size_t)b * N * 3;

    for (int i = tid; i < N; i += 1024) {
        sx[i] = p[i * 3 + 0];
        sy[i] = p[i * 3 + 1];
        sz[i] = p[i * 3 + 2];
    }
    float md[16];
#pragma unroll
    for (int j = 0; j < 16; ++j) md[j] = 1e10f;

    if (tid == 0) { g_fpsidx[b * npoint] = 0; s_last = 0; }
    __syncthreads();

    for (int it = 1; it < npoint; ++it) {
        int last = s_last;
        float lx = sx[last], ly = sy[last], lz = sz[last];
        unsigned long long best = 0ull;
#pragma unroll
        for (int j = 0; j < 16; ++j) {
            int i = tid + j * 1024;
            if (i < N) {
                float dx = __fsub_rn(sx[i], lx);
                float dy = __fsub_rn(sy[i], ly);
                float dz = __fsub_rn(sz[i], lz);
                float d = d2_exact(dx, dy, dz);
                float m = fminf(md[j], d);
                md[j] = m;
                unsigned long long key =
                    ((unsigned long long)__float_as_uint(m) << 32) |
                    (unsigned long long)(0xFFFFFFFFu - (unsigned)i);
                if (key > best) best = key;
            }
        }
#pragma unroll
        for (int off = 16; off; off >>= 1) {
            unsigned long long o = __shfl_down_sync(0xffffffffu, best, off);
            if (o > best) best = o;
        }
        if ((tid & 31) == 0) warpbest[tid >> 5] = best;
        __syncthreads();
        if (tid < 32) {
            unsigned long long v = warpbest[tid];
#pragma unroll
            for (int off = 16; off; off >>= 1) {
                unsigned long long o = __shfl_down_sync(0xffffffffu, v, off);
                if (o > v) v = o;
            }
            if (tid == 0) {
                int sel = (int)(0xFFFFFFFFu - (unsigned)(v & 0xFFFFFFFFull));
                s_last = sel;
                g_fpsidx[b * npoint + it] = sel;
            }
        }
        __syncthreads();
    }
}

// ---------------- gather query xyz ------------------------------------------
__global__ void k_query(const float* __restrict__ ext, int scode, int qcode,
                        int Q, int Ns) {
    int i = blockIdx.x * blockDim.x + threadIdx.x;
    if (i >= 2 * Q) return;
    int b = i / Q;
    const float* sup = fbufc(scode, ext) + (size_t)b * Ns * 3;
    int id = g_fpsidx[i];
    float* o = fbufw(qcode, nullptr) + (size_t)i * 3;
    o[0] = sup[id * 3 + 0];
    o[1] = sup[id * 3 + 1];
    o[2] = sup[id * 3 + 2];
}

// ---------------- ball query: warp per query --------------------------------
// First 32 in-radius indices in ascending index order, padded with first hit.
__global__ void k_ball(const float* __restrict__ ext, int scode, int qcode,
                       int Q, int Ns, float r2) {
    int gw = (blockIdx.x * blockDim.x + threadIdx.x) >> 5;
    int lane = threadIdx.x & 31;
    if (gw >= 2 * Q) return;
    int b = gw / Q;
    const float* qp = fbufc(qcode, nullptr) + (size_t)gw * 3;
    float qx = qp[0], qy = qp[1], qz = qp[2];
    const float* sp = fbufc(scode, ext) + (size_t)b * Ns * 3;
    int* o = g_ballidx + (size_t)gw * 32;

    int cnt = 0, first = 0;
    for (int base = 0; base < Ns; base += 32) {
        int i = base + lane;                       // Ns is always a mult of 32
        float dx = __fsub_rn(qx, sp[i * 3 + 0]);
        float dy = __fsub_rn(qy, sp[i * 3 + 1]);
        float dz = __fsub_rn(qz, sp[i * 3 + 2]);
        bool hit = d2_exact(dx, dy, dz) < r2;
        unsigned m = __ballot_sync(0xffffffffu, hit);
        if (cnt == 0 && m) first = base + __ffs(m) - 1;
        if (hit) {
            int pos = cnt + __popc(m & ((1u << lane) - 1u));
            if (pos < 32) o[pos] = i;
        }
        cnt += __popc(m);
        if (cnt >= 32) break;
    }
    for (int pos = cnt + lane; pos < 32; pos += 32) o[pos] = first;
}

// ---------------- gather f0 = concat(dp, feats[idx])  [B, 3+C, Q*32] --------
__global__ void k_gather(const float* __restrict__ ext, int scode, int qcode,
                         int ficode, int C, int Q, int Ns) {
    long long QS = (long long)Q * 32;
    int n = blockIdx.x * blockDim.x + threadIdx.x;
    if (n >= QS) return;
    int b = blockIdx.y;
    int q = n >> 5;
    int id = g_ballidx[((size_t)b * Q + q) * 32 + (n & 31)];
    const float* sup = fbufc(scode, ext) + ((size_t)b * Ns + id) * 3;
    const float* qp = fbufc(qcode, nullptr) + ((size_t)b * Q + q) * 3;
    float* o = g_f0 + (size_t)b * (3 + C) * QS + n;
    o[0]      = __fsub_rn(sup[0], qp[0]);
    o[QS]     = __fsub_rn(sup[1], qp[1]);
    o[2 * QS] = __fsub_rn(sup[2], qp[2]);
    const float* fi = fbufc(ficode, nullptr) + (size_t)b * C * Ns + id;
    for (int c = 0; c < C; ++c)
        o[(size_t)(c + 3) * QS] = fi[(size_t)c * Ns];
}

// ---------------- GEMM: Y = relu(W @ X + bias), optional fused max-pool -----
// W [M,K] row-major, X [K,Nn] per batch, 64x128 block tile, 4x8 thread tile.
// M % 64 == 0 and Nn % 128 == 0 always hold for these shapes.
template <bool POOL>
__global__ __launch_bounds__(256)
void k_gemm(const float* __restrict__ Wt, const float* __restrict__ bias,
            int xcode, int ycode, float* yext, int M, int K, long long Nn) {
    __shared__ __align__(16) float As[16][64];
    __shared__ __align__(16) float Bs[16][128];
    int b = blockIdx.z;
    const float* X = fbufc(xcode, nullptr) + (size_t)b * K * Nn;
    int tid = threadIdx.x;
    int tm = tid >> 4, tn = tid & 15;
    int rowBase = blockIdx.y * 64;
    long long colBase = (long long)blockIdx.x * 128;

    float acc[4][8];
#pragma unroll
    for (int i = 0; i < 4; ++i)
#pragma unroll
        for (int j = 0; j < 8; ++j) acc[i][j] = 0.f;

    for (int k0 = 0; k0 < K; k0 += 16) {
#pragma unroll
        for (int t = tid; t < 64 * 16; t += 256) {
            int m = t >> 4, kk = t & 15;
            As[kk][m] = (k0 + kk < K) ? Wt[(size_t)(rowBase + m) * K + k0 + kk] : 0.f;
        }
#pragma unroll
        for (int t = tid; t < 16 * 128; t += 256) {
            int kk = t >> 7, nn = t & 127;
            Bs[kk][nn] = (k0 + kk < K) ? X[(size_t)(k0 + kk) * Nn + colBase + nn] : 0.f;
        }
        __syncthreads();
#pragma unroll
        for (int kk = 0; kk < 16; ++kk) {
            float4 a4 = *reinterpret_cast<const float4*>(&As[kk][tm * 4]);
            float4 b0 = *reinterpret_cast<const float4*>(&Bs[kk][tn * 8]);
            float4 b1 = *reinterpret_cast<const float4*>(&Bs[kk][tn * 8 + 4]);
            float a[4] = {a4.x, a4.y, a4.z, a4.w};
            float bb[8] = {b0.x, b0.y, b0.z, b0.w, b1.x, b1.y, b1.z, b1.w};
#pragma unroll
            for (int i = 0; i < 4; ++i)
#pragma unroll
                for (int j = 0; j < 8; ++j)
                    acc[i][j] = fmaf(a[i], bb[j], acc[i][j]);
        }
        __syncthreads();
    }

    if (!POOL) {
        float* Y = fbufw(ycode, yext) + (size_t)b * M * Nn;
#pragma unroll
        for (int i = 0; i < 4; ++i) {
            float bv = bias[rowBase + tm * 4 + i];
            float* yr = Y + (size_t)(rowBase + tm * 4 + i) * Nn + colBase + tn * 8;
#pragma unroll
            for (int j = 0; j < 8; ++j) {
                float v = acc[i][j] + bv;
                yr[j] = v > 0.f ? v : 0.f;
            }
        }
    } else {
        // max over the 32-neighbor groups (relu/bias commute with max)
        long long Q = Nn >> 5;
        float* Y = fbufw(ycode, yext) + (size_t)b * M * Q;
#pragma unroll
        for (int i = 0; i < 4; ++i) {
            float m = acc[i][0];
#pragma unroll
            for (int j = 1; j < 8; ++j) m = fmaxf(m, acc[i][j]);
            m = fmaxf(m, __shfl_xor_sync(0xffffffffu, m, 1));
            m = fmaxf(m, __shfl_xor_sync(0xffffffffu, m, 2));
            if ((tn & 3) == 0) {
                float v = m + bias[rowBase + tm * 4 + i];
                long long q = (colBase >> 5) + (tn >> 2);
                Y[(size_t)(rowBase + tm * 4 + i) * Q + q] = v > 0.f ? v : 0.f;
            }
        }
    }
}

// ---------------------------------------------------------------------------
extern "C" void kernel_launch(void* const* d_in, const int* in_sizes, int n_in,
                              void* d_out, int out_size) {
    (void)in_sizes; (void)n_in; (void)out_size;
    const float* xyz = (const float*)d_in[0];
    const float* W[4][3]; const float* BV[4][3];
    {
        int p = 1;
        for (int k = 0; k < 4; ++k)
            for (int l = 0; l < 3; ++l) {
                W[k][l]  = (const float*)d_in[p++];
                BV[k][l] = (const float*)d_in[p++];
            }
    }

    // FPS stage 0 needs 192KB dynamic smem
    cudaFuncSetAttribute(k_fps, cudaFuncAttributeMaxDynamicSharedMemorySize, 196608);

    k_transpose<<<(2 * 16384 + 255) / 256, 256>>>(xyz);

    static const int   Ns[4]  = {16384, 4096, 1024, 256};
    static const int   CIN[4] = {6, 131, 259, 515};
    static const int   C1[4]  = {64, 128, 256, 512};
    static const int   C2[4]  = {64, 128, 256, 512};
    static const int   C3[4]  = {128, 256, 512, 1024};
    // r*r rounded exactly as JAX does (double product -> float)
    static const float R2[4]  = {(float)(0.1 * 0.1), (float)(0.2 * 0.2),
                                 (float)(0.4 * 0.4), (float)(0.8 * 0.8)};
    static const int supc[4] = {-1, 6, 7, 6};   // support xyz buffer
    static const int qc[4]   = {6, 7, 6, 7};    // query   xyz buffer
    static const int fic[4]  = {5, 3, 4, 3};    // feats-in buffer
    static const int foc[4]  = {3, 4, 3, -1};   // pooled feats-out (last -> d_out)

    for (int k = 0; k < 4; ++k) {
        int N = Ns[k], Q = N / 4;
        long long Nn = (long long)Q * 32;

        k_fps<<<2, 1024, (size_t)3 * N * 4>>>(xyz, supc[k], N, Q);
        k_query<<<(2 * Q + 255) / 256, 256>>>(xyz, supc[k], qc[k], Q, N);
        k_ball<<<(2 * Q * 32 + 255) / 256, 256>>>(xyz, supc[k], qc[k], Q, N, R2[k]);
        k_gather<<<dim3((unsigned)((Nn + 255) / 256), 2), 256>>>(
            xyz, supc[k], qc[k], fic[k], CIN[k] - 3, Q, N);

        dim3 g1((unsigned)(Nn / 128), C1[k] / 64, 2);
        k_gemm<false><<<g1, 256>>>(W[k][0], BV[k][0], 0, 1, nullptr,
                                   C1[k], CIN[k], Nn);
        dim3 g2((unsigned)(Nn / 128), C2[k] / 64, 2);
        k_gemm<false><<<g2, 256>>>(W[k][1], BV[k][1], 1, 2, nullptr,
                                   C2[k], C1[k], Nn);
        dim3 g3((unsigned)(Nn / 128), C3[k] / 64, 2);
        k_gemm<true><<<g3, 256>>>(W[k][2], BV[k][2], 2, foc[k],
                                  (float*)d_out, C3[k], C2[k], Nn);
    }
}

// round 3
// speedup vs baseline: 1.3611x; 1.3611x over previous
#include <cuda_runtime.h>
#include <cuda_bf16.h>
#include <cooperative_groups.h>

namespace cg = cooperative_groups;

// ---------------------------------------------------------------------------
// PointNet++ encoder, B=2, N=16384, 4 SA stages (stride 4, nsample 32)
// ---------------------------------------------------------------------------

// ---------------- scratch buffers (device globals; no allocs allowed) ------
__device__ float g_f0[8585216];    // gathered features  max: 2*131*1024*32
__device__ float g_h1[16777216];   // layer-1 out        max: 2*64*4096*32
__device__ float g_h2[16777216];   // layer-2 out        max: 2*64*4096*32
__device__ float g_fA[1048576];    // pooled feats ping  max: 2*128*4096
__device__ float g_fB[1048576];    // pooled feats pong
__device__ float g_feats0[98304];  // xyz^T              2*3*16384
__device__ float g_q0[24576];      // query xyz ping     2*4096*3
__device__ float g_q1[24576];      // query xyz pong
__device__ int   g_fpsidx[8192];   // 2*4096
__device__ int   g_ballidx[262144];// 2*4096*32

__device__ __forceinline__ const float* fbufc(int code, const float* ext) {
    switch (code) {
        case 0: return g_f0;  case 1: return g_h1;  case 2: return g_h2;
        case 3: return g_fA;  case 4: return g_fB;  case 5: return g_feats0;
        case 6: return g_q0;  case 7: return g_q1;  default: return ext;
    }
}
__device__ __forceinline__ float* fbufw(int code, float* ext) {
    switch (code) {
        case 0: return g_f0;  case 1: return g_h1;  case 2: return g_h2;
        case 3: return g_fA;  case 4: return g_fB;  case 5: return g_feats0;
        case 6: return g_q0;  case 7: return g_q1;  default: return ext;
    }
}

// d2 exactly as JAX computes it: ((dx*dx + dy*dy) + dz*dz), no FMA contraction
__device__ __forceinline__ float d2_exact(float dx, float dy, float dz) {
    return __fadd_rn(__fadd_rn(__fmul_rn(dx, dx), __fmul_rn(dy, dy)),
                     __fmul_rn(dz, dz));
}

// ---------------- feats0 = xyz^T  [B,3,N] -----------------------------------
__global__ void k_transpose(const float* __restrict__ xyz) {
    int i = blockIdx.x * blockDim.x + threadIdx.x;
    if (i >= 2 * 16384) return;
    int b = i >> 14, n = i & 16383;
#pragma unroll
    for (int c = 0; c < 3; ++c)
        g_feats0[(b * 3 + c) * 16384 + n] = xyz[(size_t)i * 3 + c];
}

// ---------------- furthest point sampling: 8-CTA cluster per batch ----------
// Coordinates live in registers (<=4 pts/thread). Argmax candidates carry
// their coordinates through the reductions; one cluster.sync per iteration
// with parity-double-buffered DSMEM slots for the cross-CTA all-gather.
// Tie-break: smallest index via key = (md_bits<<32) | ~idx (jnp.argmax).
__global__ __cluster_dims__(8, 1, 1) __launch_bounds__(512, 1)
void k_fps_cl(const float* __restrict__ ext, int scode, int N, int npoint) {
    cg::cluster_group cluster = cg::this_cluster();
    const int rank = cluster.block_rank();
    const int b = blockIdx.x >> 3;
    const int tid = threadIdx.x;
    const int Npc = N >> 3;                 // points per CTA
    const int gbase = rank * Npc;

    __shared__ unsigned long long s_wkey[16];
    __shared__ float s_wx[16], s_wy[16], s_wz[16];
    __shared__ float s_win[3];
    // cluster-visible per-CTA best, double buffered by iteration parity
    __shared__ unsigned long long s_ckey[2];
    __shared__ float s_cx[2], s_cy[2], s_cz[2];

    const float* base = fbufc(scode, ext) + (size_t)b * N * 3;

    float px[4], py[4], pz[4], md[4];
#pragma unroll
    for (int j = 0; j < 4; ++j) {
        int i = tid + j * 512;
        md[j] = 1e10f;
        if (i < Npc) {
            const float* p = base + (size_t)(gbase + i) * 3;
            px[j] = p[0]; py[j] = p[1]; pz[j] = p[2];
        } else {
            px[j] = 0.f; py[j] = 0.f; pz[j] = 0.f;
        }
    }

    if (rank == 0 && tid == 0) g_fpsidx[b * npoint] = 0;
    // first selected point = index 0; every thread reads its coords (broadcast)
    float lx = base[0], ly = base[1], lz = base[2];

    int par = 0;
    for (int it = 1; it < npoint; ++it) {
        unsigned long long best = 0ull;
        float bx = 0.f, by = 0.f, bz = 0.f;
#pragma unroll
        for (int j = 0; j < 4; ++j) {
            int i = tid + j * 512;
            if (i < Npc) {
                float dx = __fsub_rn(px[j], lx);
                float dy = __fsub_rn(py[j], ly);
                float dz = __fsub_rn(pz[j], lz);
                float d = d2_exact(dx, dy, dz);
                float m = fminf(md[j], d);
                md[j] = m;
                unsigned long long key =
                    ((unsigned long long)__float_as_uint(m) << 32) |
                    (unsigned long long)(0xFFFFFFFFu - (unsigned)(gbase + i));
                if (key > best) { best = key; bx = px[j]; by = py[j]; bz = pz[j]; }
            }
        }
        // intra-warp reduce (key + coords payload)
#pragma unroll
        for (int off = 16; off; off >>= 1) {
            unsigned long long ok = __shfl_down_sync(0xffffffffu, best, off);
            float ox = __shfl_down_sync(0xffffffffu, bx, off);
            float oy = __shfl_down_sync(0xffffffffu, by, off);
            float oz = __shfl_down_sync(0xffffffffu, bz, off);
            if (ok > best) { best = ok; bx = ox; by = oy; bz = oz; }
        }
        if ((tid & 31) == 0) {
            int w = tid >> 5;
            s_wkey[w] = best; s_wx[w] = bx; s_wy[w] = by; s_wz[w] = bz;
        }
        __syncthreads();
        // warp 0: reduce 16 warp-bests, publish CTA best to cluster slot
        if (tid < 32) {
            unsigned long long k2 = (tid < 16) ? s_wkey[tid] : 0ull;
            float x2 = (tid < 16) ? s_wx[tid] : 0.f;
            float y2 = (tid < 16) ? s_wy[tid] : 0.f;
            float z2 = (tid < 16) ? s_wz[tid] : 0.f;
#pragma unroll
            for (int off = 8; off; off >>= 1) {
                unsigned long long ok = __shfl_down_sync(0xffffffffu, k2, off);
                float ox = __shfl_down_sync(0xffffffffu, x2, off);
                float oy = __shfl_down_sync(0xffffffffu, y2, off);
                float oz = __shfl_down_sync(0xffffffffu, z2, off);
                if (ok > k2) { k2 = ok; x2 = ox; y2 = oy; z2 = oz; }
            }
            if (tid == 0) {
                s_ckey[par] = k2; s_cx[par] = x2; s_cy[par] = y2; s_cz[par] = z2;
            }
        }
        cluster.sync();   // publishes slots (release/acquire across cluster)
        // warp 0 lanes 0-7: gather all 8 CTA bests, reduce, broadcast winner
        if (tid < 32) {
            unsigned long long k3 = 0ull;
            float x3 = 0.f, y3 = 0.f, z3 = 0.f;
            if (tid < 8) {
                unsigned long long* rk =
                    (unsigned long long*)cluster.map_shared_rank((void*)&s_ckey[par], tid);
                float* rx = (float*)cluster.map_shared_rank((void*)&s_cx[par], tid);
                float* ry = (float*)cluster.map_shared_rank((void*)&s_cy[par], tid);
                float* rz = (float*)cluster.map_shared_rank((void*)&s_cz[par], tid);
                k3 = *rk; x3 = *rx; y3 = *ry; z3 = *rz;
            }
#pragma unroll
            for (int off = 4; off; off >>= 1) {
                unsigned long long ok = __shfl_down_sync(0xffffffffu, k3, off);
                float ox = __shfl_down_sync(0xffffffffu, x3, off);
                float oy = __shfl_down_sync(0xffffffffu, y3, off);
                float oz = __shfl_down_sync(0xffffffffu, z3, off);
                if (ok > k3) { k3 = ok; x3 = ox; y3 = oy; z3 = oz; }
            }
            if (tid == 0) {
                s_win[0] = x3; s_win[1] = y3; s_win[2] = z3;
                if (rank == 0) {
                    int sel = (int)(0xFFFFFFFFu - (unsigned)(k3 & 0xFFFFFFFFull));
                    g_fpsidx[b * npoint + it] = sel;
                }
            }
        }
        __syncthreads();
        lx = s_win[0]; ly = s_win[1]; lz = s_win[2];
        par ^= 1;
    }
}

// ---------------- gather query xyz ------------------------------------------
__global__ void k_query(const float* __restrict__ ext, int scode, int qcode,
                        int Q, int Ns) {
    int i = blockIdx.x * blockDim.x + threadIdx.x;
    if (i >= 2 * Q) return;
    int b = i / Q;
    const float* sup = fbufc(scode, ext) + (size_t)b * Ns * 3;
    int id = g_fpsidx[i];
    float* o = fbufw(qcode, nullptr) + (size_t)i * 3;
    o[0] = sup[id * 3 + 0];
    o[1] = sup[id * 3 + 1];
    o[2] = sup[id * 3 + 2];
}

// ---------------- ball query: warp per query --------------------------------
__global__ void k_ball(const float* __restrict__ ext, int scode, int qcode,
                       int Q, int Ns, float r2) {
    int gw = (blockIdx.x * blockDim.x + threadIdx.x) >> 5;
    int lane = threadIdx.x & 31;
    if (gw >= 2 * Q) return;
    int b = gw / Q;
    const float* qp = fbufc(qcode, nullptr) + (size_t)gw * 3;
    float qx = qp[0], qy = qp[1], qz = qp[2];
    const float* sp = fbufc(scode, ext) + (size_t)b * Ns * 3;
    int* o = g_ballidx + (size_t)gw * 32;

    int cnt = 0, first = 0;
    for (int base = 0; base < Ns; base += 32) {
        int i = base + lane;                       // Ns is always a mult of 32
        float dx = __fsub_rn(qx, sp[i * 3 + 0]);
        float dy = __fsub_rn(qy, sp[i * 3 + 1]);
        float dz = __fsub_rn(qz, sp[i * 3 + 2]);
        bool hit = d2_exact(dx, dy, dz) < r2;
        unsigned m = __ballot_sync(0xffffffffu, hit);
        if (cnt == 0 && m) first = base + __ffs(m) - 1;
        if (hit) {
            int pos = cnt + __popc(m & ((1u << lane) - 1u));
            if (pos < 32) o[pos] = i;
        }
        cnt += __popc(m);
        if (cnt >= 32) break;
    }
    for (int pos = cnt + lane; pos < 32; pos += 32) o[pos] = first;
}

// ---------------- gather f0 = concat(dp, feats[idx])  [B, 3+C, Q*32] --------
__global__ void k_gather(const float* __restrict__ ext, int scode, int qcode,
                         int ficode, int C, int Q, int Ns) {
    long long QS = (long long)Q * 32;
    int n = blockIdx.x * blockDim.x + threadIdx.x;
    if (n >= QS) return;
    int b = blockIdx.y;
    int q = n >> 5;
    int id = g_ballidx[((size_t)b * Q + q) * 32 + (n & 31)];
    const float* sup = fbufc(scode, ext) + ((size_t)b * Ns + id) * 3;
    const float* qp = fbufc(qcode, nullptr) + ((size_t)b * Q + q) * 3;
    float* o = g_f0 + (size_t)b * (3 + C) * QS + n;
    o[0]      = __fsub_rn(sup[0], qp[0]);
    o[QS]     = __fsub_rn(sup[1], qp[1]);
    o[2 * QS] = __fsub_rn(sup[2], qp[2]);
    const float* fi = fbufc(ficode, nullptr) + (size_t)b * C * Ns + id;
#pragma unroll 4
    for (int c = 0; c < C; ++c)
        o[(size_t)(c + 3) * QS] = fi[(size_t)c * Ns];
}

// ---------------- GEMM: Y = relu(W @ X + bias), optional fused max-pool -----
// W [M,K] row-major, X [K,Nn] per batch. BN = 128 cols, TN = 8 cols/thread,
// 256 threads. BM x TM selected per layer (128x8 for M>=128, 64x4 otherwise).
template <int BM, int BK, int TM, bool POOL>
__global__ __launch_bounds__(256)
void k_gemm(const float* __restrict__ Wt, const float* __restrict__ bias,
            int xcode, int ycode, float* yext, int M, int K, long long Nn) {
    __shared__ __align__(16) float As[BK][BM];
    __shared__ __align__(16) float Bs[BK][128];
    int b = blockIdx.z;
    const float* X = fbufc(xcode, nullptr) + (size_t)b * K * Nn;
    int tid = threadIdx.x;
    int tm = tid >> 4, tn = tid & 15;
    int rowBase = blockIdx.y * BM;
    long long colBase = (long long)blockIdx.x * 128;

    float acc[TM][8];
#pragma unroll
    for (int i = 0; i < TM; ++i)
#pragma unroll
        for (int j = 0; j < 8; ++j) acc[i][j] = 0.f;

    for (int k0 = 0; k0 < K; k0 += BK) {
#pragma unroll
        for (int t = tid; t < BM * BK; t += 256) {
            int m = t / BK, kk = t % BK;
            As[kk][m] = (k0 + kk < K) ? Wt[(size_t)(rowBase + m) * K + k0 + kk] : 0.f;
        }
#pragma unroll
        for (int t = tid; t < BK * 128; t += 256) {
            int kk = t >> 7, nn = t & 127;
            Bs[kk][nn] = (k0 + kk < K) ? X[(size_t)(k0 + kk) * Nn + colBase + nn] : 0.f;
        }
        __syncthreads();
#pragma unroll
        for (int kk = 0; kk < BK; ++kk) {
            float a[TM], bb[8];
#pragma unroll
            for (int v = 0; v < TM / 4; ++v) {
                float4 a4 = *reinterpret_cast<const float4*>(&As[kk][tm * TM + 4 * v]);
                a[4 * v] = a4.x; a[4 * v + 1] = a4.y;
                a[4 * v + 2] = a4.z; a[4 * v + 3] = a4.w;
            }
            float4 b0 = *reinterpret_cast<const float4*>(&Bs[kk][tn * 8]);
            float4 b1 = *reinterpret_cast<const float4*>(&Bs[kk][tn * 8 + 4]);
            bb[0] = b0.x; bb[1] = b0.y; bb[2] = b0.z; bb[3] = b0.w;
            bb[4] = b1.x; bb[5] = b1.y; bb[6] = b1.z; bb[7] = b1.w;
#pragma unroll
            for (int i = 0; i < TM; ++i)
#pragma unroll
                for (int j = 0; j < 8; ++j)
                    acc[i][j] = fmaf(a[i], bb[j], acc[i][j]);
        }
        __syncthreads();
    }

    if (!POOL) {
        float* Y = fbufw(ycode, yext) + (size_t)b * M * Nn;
#pragma unroll
        for (int i = 0; i < TM; ++i) {
            int row = rowBase + tm * TM + i;
            float bv = bias[row];
            float* yr = Y + (size_t)row * Nn + colBase + tn * 8;
#pragma unroll
            for (int j = 0; j < 8; ++j) {
                float v = acc[i][j] + bv;
                yr[j] = v > 0.f ? v : 0.f;
            }
        }
    } else {
        // max over the 32-neighbor groups (relu/bias commute with max)
        long long Q = Nn >> 5;
        float* Y = fbufw(ycode, yext) + (size_t)b * M * Q;
#pragma unroll
        for (int i = 0; i < TM; ++i) {
            float m = acc[i][0];
#pragma unroll
            for (int j = 1; j < 8; ++j) m = fmaxf(m, acc[i][j]);
            m = fmaxf(m, __shfl_xor_sync(0xffffffffu, m, 1));
            m = fmaxf(m, __shfl_xor_sync(0xffffffffu, m, 2));
            if ((tn & 3) == 0) {
                int row = rowBase + tm * TM + i;
                float v = m + bias[row];
                long long q = (colBase >> 5) + (tn >> 2);
                Y[(size_t)row * Q + q] = v > 0.f ? v : 0.f;
            }
        }
    }
}

// ---------------------------------------------------------------------------
extern "C" void kernel_launch(void* const* d_in, const int* in_sizes, int n_in,
                              void* d_out, int out_size) {
    (void)in_sizes; (void)n_in; (void)out_size;
    const float* xyz = (const float*)d_in[0];
    const float* W[4][3]; const float* BV[4][3];
    {
        int p = 1;
        for (int k = 0; k < 4; ++k)
            for (int l = 0; l < 3; ++l) {
                W[k][l]  = (const float*)d_in[p++];
                BV[k][l] = (const float*)d_in[p++];
            }
    }

    k_transpose<<<(2 * 16384 + 255) / 256, 256>>>(xyz);

    static const int   Ns[4]  = {16384, 4096, 1024, 256};
    static const int   CIN[4] = {6, 131, 259, 515};
    static const int   C1[4]  = {64, 128, 256, 512};
    static const int   C2[4]  = {64, 128, 256, 512};
    static const int   C3[4]  = {128, 256, 512, 1024};
    // r*r rounded exactly as JAX does (double product -> float)
    static const float R2[4]  = {(float)(0.1 * 0.1), (float)(0.2 * 0.2),
                                 (float)(0.4 * 0.4), (float)(0.8 * 0.8)};
    static const int supc[4] = {-1, 6, 7, 6};   // support xyz buffer
    static const int qc[4]   = {6, 7, 6, 7};    // query   xyz buffer
    static const int fic[4]  = {5, 3, 4, 3};    // feats-in buffer
    static const int foc[4]  = {3, 4, 3, -1};   // pooled feats-out (last -> d_out)

    auto gemm = [&](const float* Wp, const float* bp, int xc, int yc, float* ye,
                    int M, int K, long long Nn, bool pool) {
        if (M >= 128) {
            dim3 g((unsigned)(Nn / 128), M / 128, 2);
            if (pool) k_gemm<128, 8, 8, true ><<<g, 256>>>(Wp, bp, xc, yc, ye, M, K, Nn);
            else      k_gemm<128, 8, 8, false><<<g, 256>>>(Wp, bp, xc, yc, ye, M, K, Nn);
        } else {
            dim3 g((unsigned)(Nn / 128), M / 64, 2);
            if (pool) k_gemm<64, 16, 4, true ><<<g, 256>>>(Wp, bp, xc, yc, ye, M, K, Nn);
            else      k_gemm<64, 16, 4, false><<<g, 256>>>(Wp, bp, xc, yc, ye, M, K, Nn);
        }
    };

    for (int k = 0; k < 4; ++k) {
        int N = Ns[k], Q = N / 4;
        long long Nn = (long long)Q * 32;

        k_fps_cl<<<16, 512>>>(xyz, supc[k], N, Q);
        k_query<<<(2 * Q + 255) / 256, 256>>>(xyz, supc[k], qc[k], Q, N);
        k_ball<<<(2 * Q * 32 + 255) / 256, 256>>>(xyz, supc[k], qc[k], Q, N, R2[k]);
        k_gather<<<dim3((unsigned)((Nn + 255) / 256), 2), 256>>>(
            xyz, supc[k], qc[k], fic[k], CIN[k] - 3, Q, N);

        gemm(W[k][0], BV[k][0], 0, 1, nullptr,      C1[k], CIN[k], Nn, false);
        gemm(W[k][1], BV[k][1], 1, 2, nullptr,      C2[k], C1[k],  Nn, false);
        gemm(W[k][2], BV[k][2], 2, foc[k],
             (float*)d_out,                         C3[k], C2[k],  Nn, true);
    }
}